// round 1
// baseline (speedup 1.0000x reference)
#include <cuda_runtime.h>
#include <cuda_bf16.h>
#include <cstdint>

// ---------------------------------------------------------------------------
// Problem constants
// ---------------------------------------------------------------------------
#define BQ    8192
#define FD    1024
#define HH    16
#define DD    64
#define SS    5
#define LW    3
#define CC    1000
#define GD    512
#define CSUM  1984   // 64+128+256+512+1024

// ---------------------------------------------------------------------------
// Scratch (device globals; no runtime allocation allowed)
// ---------------------------------------------------------------------------
__device__ float g_MK[FD * CSUM];          // Wk @ Ws_i  (f-major, concat cols)
__device__ float g_MV[FD * CSUM];          // Wv @ Ws_i
__device__ float g_fbk[SS * FD];           // fused K bias per scale
__device__ float g_fbv[SS * FD];           // fused V bias per scale
__device__ float g_K[(size_t)BQ * SS * FD];  // (b, s, f)
__device__ float g_V[(size_t)BQ * SS * FD];
__device__ float g_Q[(size_t)BQ * FD];
__device__ float g_H[(size_t)BQ * GD];
__device__ float g_si[BQ * SS];
__device__ float g_aw[BQ * SS];

// ---------------------------------------------------------------------------
// Helpers
// ---------------------------------------------------------------------------
__device__ __forceinline__ unsigned f2tf(float x) {
    unsigned r;
    asm("cvt.rna.tf32.f32 %0, %1;" : "=r"(r) : "f"(x));
    return r;
}
__device__ __forceinline__ float wredsum(float v) {
    #pragma unroll
    for (int o = 16; o; o >>= 1) v += __shfl_xor_sync(0xffffffffu, v, o);
    return v;
}

// ---------------------------------------------------------------------------
// tf32 mma.sync GEMM:  C[m,n] = sum_k A[m,k] * B(n,k)  (+ bias[n])
//   BNN=false (TN): B is row-major [N,K]   (weights, fused weights)
//   BNN=true  (NN): B is row-major [K,N]   (prep: Ws_i)
// Tiles: BM=128, BN=64, BK=32, 256 threads, 8 warps (4x2), warp tile 32x32.
// ---------------------------------------------------------------------------
template<bool BNN>
__global__ void __launch_bounds__(256) gemm_tf32_kernel(
    const float* __restrict__ A, int lda,
    const float* __restrict__ B, int ldb,
    const float* __restrict__ bias,
    float* __restrict__ C, int ldc,
    int K)
{
    __shared__ float As[128 * 36];
    __shared__ float Bs[64 * 36];

    const int bm = blockIdx.y * 128;
    const int bn = blockIdx.x * 64;
    const int tid  = threadIdx.x;
    const int warp = tid >> 5, lane = tid & 31;
    const int wm = (warp & 3) * 32;
    const int wn = (warp >> 2) * 32;
    const int g = lane >> 2, t = lane & 3;

    float acc[2][4][4];
    #pragma unroll
    for (int i = 0; i < 2; i++)
        #pragma unroll
        for (int j = 0; j < 4; j++)
            #pragma unroll
            for (int r = 0; r < 4; r++) acc[i][j][r] = 0.f;

    const int arow = tid >> 3;
    const int acol = (tid & 7) * 4;

    for (int kt = 0; kt < K; kt += 32) {
        // ---- load A tile (128x32), convert to tf32 ----
        #pragma unroll
        for (int r = 0; r < 4; r++) {
            const float4 v = *(const float4*)(A + (size_t)(bm + arow + 32 * r) * lda + kt + acol);
            float4 w;
            w.x = __uint_as_float(f2tf(v.x));
            w.y = __uint_as_float(f2tf(v.y));
            w.z = __uint_as_float(f2tf(v.z));
            w.w = __uint_as_float(f2tf(v.w));
            *(float4*)(&As[(arow + 32 * r) * 36 + acol]) = w;
        }
        // ---- load B tile into Bs[n][k] ----
        if (BNN) {
            #pragma unroll
            for (int r = 0; r < 2; r++) {
                const int kk = (tid >> 4) + 16 * r;
                const int nn = (tid & 15) * 4;
                const float4 v = *(const float4*)(B + (size_t)(kt + kk) * ldb + bn + nn);
                Bs[(nn + 0) * 36 + kk] = __uint_as_float(f2tf(v.x));
                Bs[(nn + 1) * 36 + kk] = __uint_as_float(f2tf(v.y));
                Bs[(nn + 2) * 36 + kk] = __uint_as_float(f2tf(v.z));
                Bs[(nn + 3) * 36 + kk] = __uint_as_float(f2tf(v.w));
            }
        } else {
            #pragma unroll
            for (int r = 0; r < 2; r++) {
                const int nn = (tid >> 3) + 32 * r;
                const float4 v = *(const float4*)(B + (size_t)(bn + nn) * ldb + kt + acol);
                float4 w;
                w.x = __uint_as_float(f2tf(v.x));
                w.y = __uint_as_float(f2tf(v.y));
                w.z = __uint_as_float(f2tf(v.z));
                w.w = __uint_as_float(f2tf(v.w));
                *(float4*)(&Bs[nn * 36 + acol]) = w;
            }
        }
        __syncthreads();

        #pragma unroll
        for (int ks = 0; ks < 4; ks++) {
            const int k0 = ks * 8;
            unsigned af[2][4], bf[4][2];
            #pragma unroll
            for (int i = 0; i < 2; i++) {
                const int r0 = wm + i * 16;
                af[i][0] = __float_as_uint(As[(r0 + g    ) * 36 + k0 + t]);
                af[i][1] = __float_as_uint(As[(r0 + 8 + g) * 36 + k0 + t]);
                af[i][2] = __float_as_uint(As[(r0 + g    ) * 36 + k0 + t + 4]);
                af[i][3] = __float_as_uint(As[(r0 + 8 + g) * 36 + k0 + t + 4]);
            }
            #pragma unroll
            for (int j = 0; j < 4; j++) {
                const int c0 = wn + j * 8;
                bf[j][0] = __float_as_uint(Bs[(c0 + g) * 36 + k0 + t]);
                bf[j][1] = __float_as_uint(Bs[(c0 + g) * 36 + k0 + t + 4]);
            }
            #pragma unroll
            for (int i = 0; i < 2; i++)
                #pragma unroll
                for (int j = 0; j < 4; j++)
                    asm volatile(
                        "mma.sync.aligned.m16n8k8.row.col.f32.tf32.tf32.f32 "
                        "{%0,%1,%2,%3},{%4,%5,%6,%7},{%8,%9},{%0,%1,%2,%3};\n"
                        : "+f"(acc[i][j][0]), "+f"(acc[i][j][1]),
                          "+f"(acc[i][j][2]), "+f"(acc[i][j][3])
                        : "r"(af[i][0]), "r"(af[i][1]), "r"(af[i][2]), "r"(af[i][3]),
                          "r"(bf[j][0]), "r"(bf[j][1]));
        }
        __syncthreads();
    }

    // ---- epilogue ----
    #pragma unroll
    for (int i = 0; i < 2; i++) {
        #pragma unroll
        for (int j = 0; j < 4; j++) {
            const int row = bm + wm + i * 16 + g;
            const int col = bn + wn + j * 8 + t * 2;
            float b0 = 0.f, b1 = 0.f;
            if (bias) { b0 = bias[col]; b1 = bias[col + 1]; }
            float2 v0 = make_float2(acc[i][j][0] + b0, acc[i][j][1] + b1);
            float2 v1 = make_float2(acc[i][j][2] + b0, acc[i][j][3] + b1);
            *(float2*)(C + (size_t)row * ldc + col) = v0;
            *(float2*)(C + (size_t)(row + 8) * ldc + col) = v1;
        }
    }
}

// ---------------------------------------------------------------------------
// Fused biases: fb[i][f] = b[f] + sum_j W[f][j] * (bs[i][j] + semb[i][j])
// one warp per output; gridDim.x = (2*S*FD)/8 = 1280, 256 threads
// ---------------------------------------------------------------------------
__global__ void __launch_bounds__(256) fbias_kernel(
    const float* __restrict__ Wk, const float* __restrict__ bk,
    const float* __restrict__ Wv, const float* __restrict__ bv,
    const float* __restrict__ bs, const float* __restrict__ semb)
{
    const int gw   = blockIdx.x * 8 + (threadIdx.x >> 5);
    const int lane = threadIdx.x & 31;
    const int which = gw / (SS * FD);
    const int rem   = gw - which * (SS * FD);
    const int i = rem >> 10;
    const int f = rem & 1023;
    const float* W = which ? Wv : Wk;
    const float* Wr  = W + (size_t)f * FD;
    const float* bsr = bs + i * FD;
    const float* ser = semb + i * FD;
    float sum = 0.f;
    for (int j = lane; j < FD; j += 32) sum += Wr[j] * (bsr[j] + ser[j]);
    sum = wredsum(sum);
    if (lane == 0) {
        if (which) g_fbv[rem] = sum + bv[f];
        else       g_fbk[rem] = sum + bk[f];
    }
}

// ---------------------------------------------------------------------------
// Attention + scale importance. One block (256 thr) per batch row b.
// si[b][s] = mean_h || sum_w softmax_w( Q.K_route /(8*|T|) ) * V_route ||_2
// ---------------------------------------------------------------------------
__global__ void __launch_bounds__(256) attn_kernel(
    const int* __restrict__ routes, const float* __restrict__ tptr)
{
    const int b = blockIdx.x;
    __shared__ float Qs[FD];
    __shared__ float Ks[SS * FD];
    __shared__ float Vs[SS * FD];
    __shared__ float ssi[SS];
    __shared__ int   rts[SS * LW];
    const int tid = threadIdx.x;

    ((float4*)Qs)[tid] = ((const float4*)(g_Q + (size_t)b * FD))[tid];
    const float4* k4 = (const float4*)(g_K + (size_t)b * SS * FD);
    const float4* v4 = (const float4*)(g_V + (size_t)b * SS * FD);
    #pragma unroll
    for (int i = 0; i < 5; i++) {
        ((float4*)Ks)[tid + 256 * i] = k4[tid + 256 * i];
        ((float4*)Vs)[tid + 256 * i] = v4[tid + 256 * i];
    }
    if (tid < SS * LW) rts[tid] = routes[tid];
    if (tid < SS) ssi[tid] = 0.f;
    __syncthreads();

    const float sc_mul = 1.0f / (8.0f * fabsf(*tptr));
    const int warp = tid >> 5, lane = tid & 31;

    for (int p = warp; p < HH * SS; p += 8) {
        const int h = p / SS, s = p - (p / SS) * SS;
        const float q0 = Qs[h * DD + lane];
        const float q1 = Qs[h * DD + 32 + lane];
        float scw[LW]; int jr[LW];
        #pragma unroll
        for (int w = 0; w < LW; w++) {
            const int j = rts[s * LW + w];
            jr[w] = j;
            const float* kh = Ks + j * FD + h * DD;
            float d = q0 * kh[lane] + q1 * kh[lane + 32];
            d = wredsum(d);
            scw[w] = d * sc_mul;
        }
        const float m = fmaxf(scw[0], fmaxf(scw[1], scw[2]));
        float e0 = expf(scw[0] - m), e1 = expf(scw[1] - m), e2 = expf(scw[2] - m);
        const float inv = 1.0f / (e0 + e1 + e2);
        e0 *= inv; e1 *= inv; e2 *= inv;
        float o0 = 0.f, o1 = 0.f;
        {
            const float* vh = Vs + jr[0] * FD + h * DD;
            o0 += e0 * vh[lane]; o1 += e0 * vh[lane + 32];
        }
        {
            const float* vh = Vs + jr[1] * FD + h * DD;
            o0 += e1 * vh[lane]; o1 += e1 * vh[lane + 32];
        }
        {
            const float* vh = Vs + jr[2] * FD + h * DD;
            o0 += e2 * vh[lane]; o1 += e2 * vh[lane + 32];
        }
        float n2 = o0 * o0 + o1 * o1;
        n2 = wredsum(n2);
        if (lane == 0) atomicAdd(&ssi[s], sqrtf(n2));
    }
    __syncthreads();
    if (tid < SS) g_si[b * SS + tid] = ssi[tid] * (1.0f / (float)HH);
}

// ---------------------------------------------------------------------------
// Gate: LayerNorm + exact GELU + Wg2 + combine with scale_importance + softmax
// One block (128 thr) per row b. Writes attention_weights to out tail + g_aw.
// ---------------------------------------------------------------------------
__global__ void __launch_bounds__(128) gate_kernel(
    const float* __restrict__ gamma, const float* __restrict__ beta,
    const float* __restrict__ Wg2, const float* __restrict__ bg2,
    float* __restrict__ outTail)
{
    const int b = blockIdx.x, tid = threadIdx.x;
    const int warp = tid >> 5, lane = tid & 31;
    __shared__ float hs[GD];
    __shared__ float rbuf[32];

    const float4 v  = ((const float4*)(g_H + (size_t)b * GD))[tid];
    float s1 = v.x + v.y + v.z + v.w;
    float s2 = v.x * v.x + v.y * v.y + v.z * v.z + v.w * v.w;
    s1 = wredsum(s1); s2 = wredsum(s2);
    if (lane == 0) { rbuf[warp] = s1; rbuf[4 + warp] = s2; }
    __syncthreads();
    const float mu  = (rbuf[0] + rbuf[1] + rbuf[2] + rbuf[3]) * (1.0f / GD);
    const float ex2 = (rbuf[4] + rbuf[5] + rbuf[6] + rbuf[7]) * (1.0f / GD);
    const float rstd = rsqrtf(ex2 - mu * mu + 1e-5f);

    const float4 ga = ((const float4*)gamma)[tid];
    const float4 be = ((const float4*)beta)[tid];
    float4 o;
    {
        float x;
        x = (v.x - mu) * rstd * ga.x + be.x; o.x = 0.5f * x * (1.f + erff(x * 0.70710678118f));
        x = (v.y - mu) * rstd * ga.y + be.y; o.y = 0.5f * x * (1.f + erff(x * 0.70710678118f));
        x = (v.z - mu) * rstd * ga.z + be.z; o.z = 0.5f * x * (1.f + erff(x * 0.70710678118f));
        x = (v.w - mu) * rstd * ga.w + be.w; o.w = 0.5f * x * (1.f + erff(x * 0.70710678118f));
    }
    ((float4*)hs)[tid] = o;
    __syncthreads();

    float p[SS] = {0.f, 0.f, 0.f, 0.f, 0.f};
    #pragma unroll
    for (int r = 0; r < 4; r++) {
        const float x = hs[tid + 128 * r];
        #pragma unroll
        for (int s = 0; s < SS; s++) p[s] += x * Wg2[s * GD + tid + 128 * r];
    }
    #pragma unroll
    for (int s = 0; s < SS; s++) p[s] = wredsum(p[s]);
    if (lane == 0)
        #pragma unroll
        for (int s = 0; s < SS; s++) rbuf[8 + warp * SS + s] = p[s];
    __syncthreads();

    if (tid == 0) {
        float cs[SS];
        #pragma unroll
        for (int s = 0; s < SS; s++) {
            const float gl = rbuf[8 + s] + rbuf[13 + s] + rbuf[18 + s] + rbuf[23 + s] + bg2[s];
            cs[s] = 0.7f * g_si[b * SS + s] + 0.3f * gl;
        }
        float m = cs[0];
        #pragma unroll
        for (int s = 1; s < SS; s++) m = fmaxf(m, cs[s]);
        float e[SS], tot = 0.f;
        #pragma unroll
        for (int s = 0; s < SS; s++) { e[s] = expf(cs[s] - m); tot += e[s]; }
        const float inv = 1.0f / tot;
        #pragma unroll
        for (int s = 0; s < SS; s++) {
            const float w = e[s] * inv;
            g_aw[b * SS + s] = w;
            outTail[(size_t)b * SS + s] = w;
        }
    }
}

// ---------------------------------------------------------------------------
// combined_logits[b,c] = sum_s aw[b,s] * logits_s[b,c]   (float4 over C=1000)
// ---------------------------------------------------------------------------
__global__ void __launch_bounds__(256) combine_kernel(
    const float* __restrict__ l0, const float* __restrict__ l1,
    const float* __restrict__ l2, const float* __restrict__ l3,
    const float* __restrict__ l4, float* __restrict__ out)
{
    const int t = blockIdx.x * blockDim.x + threadIdx.x;
    if (t >= BQ * (CC / 4)) return;
    const int b = t / (CC / 4);
    const int c = t - b * (CC / 4);
    const float w0 = g_aw[b * SS + 0], w1 = g_aw[b * SS + 1], w2 = g_aw[b * SS + 2];
    const float w3 = g_aw[b * SS + 3], w4 = g_aw[b * SS + 4];
    const size_t idx = (size_t)b * (CC / 4) + c;
    const float4 a0 = ((const float4*)l0)[idx];
    const float4 a1 = ((const float4*)l1)[idx];
    const float4 a2 = ((const float4*)l2)[idx];
    const float4 a3 = ((const float4*)l3)[idx];
    const float4 a4 = ((const float4*)l4)[idx];
    float4 r;
    r.x = w0 * a0.x + w1 * a1.x + w2 * a2.x + w3 * a3.x + w4 * a4.x;
    r.y = w0 * a0.y + w1 * a1.y + w2 * a2.y + w3 * a3.y + w4 * a4.y;
    r.z = w0 * a0.z + w1 * a1.z + w2 * a2.z + w3 * a3.z + w4 * a4.z;
    r.w = w0 * a0.w + w1 * a1.w + w2 * a2.w + w3 * a3.w + w4 * a4.w;
    ((float4*)out)[idx] = r;
}

// ---------------------------------------------------------------------------
// kernel_launch
// ---------------------------------------------------------------------------
extern "C" void kernel_launch(void* const* d_in, const int* in_sizes, int n_in,
                              void* d_out, int out_size)
{
    (void)in_sizes; (void)n_in; (void)out_size;
    const float* features = (const float*)d_in[0];
    const float* sf[SS]     = {(const float*)d_in[1],  (const float*)d_in[2],
                               (const float*)d_in[3],  (const float*)d_in[4],
                               (const float*)d_in[5]};
    const float* logits[SS] = {(const float*)d_in[6],  (const float*)d_in[7],
                               (const float*)d_in[8],  (const float*)d_in[9],
                               (const float*)d_in[10]};
    const float* Ws[SS]     = {(const float*)d_in[11], (const float*)d_in[12],
                               (const float*)d_in[13], (const float*)d_in[14],
                               (const float*)d_in[15]};
    const float* bs   = (const float*)d_in[16];
    const float* semb = (const float*)d_in[17];
    const float* Wq   = (const float*)d_in[18];
    const float* bq   = (const float*)d_in[19];
    const float* Wk   = (const float*)d_in[20];
    const float* bk   = (const float*)d_in[21];
    const float* Wv   = (const float*)d_in[22];
    const float* bv   = (const float*)d_in[23];
    const float* Wg1  = (const float*)d_in[24];
    const float* bg1  = (const float*)d_in[25];
    const float* gam  = (const float*)d_in[26];
    const float* bet  = (const float*)d_in[27];
    const float* Wg2  = (const float*)d_in[28];
    const float* bg2  = (const float*)d_in[29];
    const float* temp = (const float*)d_in[30];
    const int*   routes = (const int*)d_in[31];

    float *MK, *MV, *fbk, *fbv, *Kb, *Vb, *Qb, *Hb;
    cudaGetSymbolAddress((void**)&MK,  g_MK);
    cudaGetSymbolAddress((void**)&MV,  g_MV);
    cudaGetSymbolAddress((void**)&fbk, g_fbk);
    cudaGetSymbolAddress((void**)&fbv, g_fbv);
    cudaGetSymbolAddress((void**)&Kb,  g_K);
    cudaGetSymbolAddress((void**)&Vb,  g_V);
    cudaGetSymbolAddress((void**)&Qb,  g_Q);
    cudaGetSymbolAddress((void**)&Hb,  g_H);

    static const int SC[SS]  = {64, 128, 256, 512, 1024};
    static const int OFF[SS] = {0, 64, 192, 448, 960};

    // 1) Fused weights: MK_i = Wk @ Ws_i, MV_i = Wv @ Ws_i  (NN GEMM, K=1024)
    for (int i = 0; i < SS; i++) {
        dim3 grid(SC[i] / 64, FD / 128);
        gemm_tf32_kernel<true><<<grid, 256>>>(Wk, FD, Ws[i], SC[i], nullptr,
                                              MK + OFF[i], CSUM, FD);
        gemm_tf32_kernel<true><<<grid, 256>>>(Wv, FD, Ws[i], SC[i], nullptr,
                                              MV + OFF[i], CSUM, FD);
    }
    // 2) Fused biases
    fbias_kernel<<<(2 * SS * FD) / 8, 256>>>(Wk, bk, Wv, bv, bs, semb);

    // 3) K_i = sf_i @ MK_i^T + fbk_i ; V_i likewise  (TN GEMM, K=sc)
    for (int i = 0; i < SS; i++) {
        dim3 grid(FD / 64, BQ / 128);
        gemm_tf32_kernel<false><<<grid, 256>>>(sf[i], SC[i], MK + OFF[i], CSUM,
                                               fbk + i * FD, Kb + i * FD, SS * FD, SC[i]);
        gemm_tf32_kernel<false><<<grid, 256>>>(sf[i], SC[i], MV + OFF[i], CSUM,
                                               fbv + i * FD, Vb + i * FD, SS * FD, SC[i]);
    }
    // 4) Q = features @ Wq^T + bq ; H = features @ Wg1^T + bg1
    gemm_tf32_kernel<false><<<dim3(FD / 64, BQ / 128), 256>>>(features, FD, Wq, FD,
                                                              bq, Qb, FD, FD);
    gemm_tf32_kernel<false><<<dim3(GD / 64, BQ / 128), 256>>>(features, FD, Wg1, FD,
                                                              bg1, Hb, GD, FD);
    // 5) Attention + scale importance
    attn_kernel<<<BQ, 256>>>(routes, temp);

    // 6) Gate + combined softmax -> attention_weights (also to output tail)
    float* out = (float*)d_out;
    gate_kernel<<<BQ, 128>>>(gam, bet, Wg2, bg2, out + (size_t)BQ * CC);

    // 7) combined_logits
    combine_kernel<<<(BQ * (CC / 4) + 255) / 256, 256>>>(logits[0], logits[1], logits[2],
                                                         logits[3], logits[4], out);
}

// round 2
// speedup vs baseline: 1.5713x; 1.5713x over previous
#include <cuda_runtime.h>
#include <cuda_bf16.h>
#include <cstdint>

#define BQ    8192
#define FD    1024
#define HH    16
#define DD    64
#define SS    5
#define LW    3
#define CC    1000
#define GD    512
#define CSUM  1984   // 64+128+256+512+1024

// ---------------------------------------------------------------------------
// Scratch
// ---------------------------------------------------------------------------
__device__ float g_MK[FD * CSUM];
__device__ float g_MV[FD * CSUM];
__device__ float g_fbk[SS * FD];
__device__ float g_fbv[SS * FD];
__device__ float g_K[(size_t)BQ * SS * FD];
__device__ float g_V[(size_t)BQ * SS * FD];
__device__ float g_Q[(size_t)BQ * FD];
__device__ float g_H[(size_t)BQ * GD];
__device__ float g_si[BQ * SS];
__device__ float g_aw[BQ * SS];

// ---------------------------------------------------------------------------
// Helpers
// ---------------------------------------------------------------------------
__device__ __forceinline__ unsigned f2tf(float x) {
    unsigned r;
    asm("cvt.rna.tf32.f32 %0, %1;" : "=r"(r) : "f"(x));
    return r;
}
__device__ __forceinline__ float wredsum(float v) {
    #pragma unroll
    for (int o = 16; o; o >>= 1) v += __shfl_xor_sync(0xffffffffu, v, o);
    return v;
}
__device__ __forceinline__ void cp16(float* s, const float* g) {
    uint32_t sa = (uint32_t)__cvta_generic_to_shared(s);
    asm volatile("cp.async.cg.shared.global [%0], [%1], 16;\n" :: "r"(sa), "l"(g));
}

// Segment descriptor for batched GEMM launches
struct SegDesc {
    const float* A;
    const float* B;
    const float* bias;
    float*       C;
    int lda, ldb, ldc, K, xStart;
};
struct SegParams { SegDesc seg[12]; };

// ---------------------------------------------------------------------------
// Batched TN GEMM, double-buffered cp.async:
//   C[m,n] = sum_k A[m,k] * B[n,k] + bias[n]
// BM=128, BN=64, BK=32, 256 thr, 8 warps (4x2), warp tile 32x32, tf32 mma.
// grid = (sum xCount, 64). Dynamic smem = 2*(128+64)*36 floats = 55296 B.
// ---------------------------------------------------------------------------
__global__ void __launch_bounds__(256) gemm_tn_batched(SegParams p, int nseg)
{
    extern __shared__ float smemDyn[];
    float* Asb = smemDyn;                 // 2 * 128*36
    float* Bsb = smemDyn + 2 * 128 * 36;  // 2 * 64*36

    const int bx = blockIdx.x;
    int si = 0;
    #pragma unroll
    for (int i = 1; i < 12; i++)
        if (i < nseg && bx >= p.seg[i].xStart) si = i;
    const SegDesc d = p.seg[si];

    const int bn = (bx - d.xStart) * 64;
    const int bm = blockIdx.y * 128;
    const int tid  = threadIdx.x;
    const int warp = tid >> 5, lane = tid & 31;
    const int wm = (warp & 3) * 32;
    const int wn = (warp >> 2) * 32;
    const int g = lane >> 2, t = lane & 3;
    const int arow = tid >> 3;
    const int acol = (tid & 7) * 4;
    const int brow = tid >> 3;          // 0..31

    float acc[2][4][4];
    #pragma unroll
    for (int i = 0; i < 2; i++)
        #pragma unroll
        for (int j = 0; j < 4; j++)
            #pragma unroll
            for (int r = 0; r < 4; r++) acc[i][j][r] = 0.f;

    const int T = d.K >> 5;   // BK=32 tiles

    // async tile loader
    auto issue = [&](int ti, int buf) {
        const int kt = ti * 32;
        float* As = Asb + buf * (128 * 36);
        float* Bs = Bsb + buf * (64 * 36);
        #pragma unroll
        for (int r = 0; r < 4; r++)
            cp16(&As[(arow + 32 * r) * 36 + acol],
                 d.A + (size_t)(bm + arow + 32 * r) * d.lda + kt + acol);
        #pragma unroll
        for (int r = 0; r < 2; r++)
            cp16(&Bs[(brow + 32 * r) * 36 + acol],
                 d.B + (size_t)(bn + brow + 32 * r) * d.ldb + kt + acol);
        asm volatile("cp.async.commit_group;\n");
    };

    issue(0, 0);

    for (int ti = 0; ti < T; ti++) {
        const int buf = ti & 1;
        if (ti + 1 < T) {
            issue(ti + 1, buf ^ 1);
            asm volatile("cp.async.wait_group 1;\n");
        } else {
            asm volatile("cp.async.wait_group 0;\n");
        }
        __syncthreads();

        const float* As = Asb + buf * (128 * 36);
        const float* Bs = Bsb + buf * (64 * 36);
        #pragma unroll
        for (int ks = 0; ks < 4; ks++) {
            const int k0 = ks * 8;
            unsigned af[2][4], bf[4][2];
            #pragma unroll
            for (int i = 0; i < 2; i++) {
                const int r0 = wm + i * 16;
                af[i][0] = __float_as_uint(As[(r0 + g    ) * 36 + k0 + t]);
                af[i][1] = __float_as_uint(As[(r0 + 8 + g) * 36 + k0 + t]);
                af[i][2] = __float_as_uint(As[(r0 + g    ) * 36 + k0 + t + 4]);
                af[i][3] = __float_as_uint(As[(r0 + 8 + g) * 36 + k0 + t + 4]);
            }
            #pragma unroll
            for (int j = 0; j < 4; j++) {
                const int c0 = wn + j * 8;
                bf[j][0] = __float_as_uint(Bs[(c0 + g) * 36 + k0 + t]);
                bf[j][1] = __float_as_uint(Bs[(c0 + g) * 36 + k0 + t + 4]);
            }
            #pragma unroll
            for (int i = 0; i < 2; i++)
                #pragma unroll
                for (int j = 0; j < 4; j++)
                    asm volatile(
                        "mma.sync.aligned.m16n8k8.row.col.f32.tf32.tf32.f32 "
                        "{%0,%1,%2,%3},{%4,%5,%6,%7},{%8,%9},{%0,%1,%2,%3};\n"
                        : "+f"(acc[i][j][0]), "+f"(acc[i][j][1]),
                          "+f"(acc[i][j][2]), "+f"(acc[i][j][3])
                        : "r"(af[i][0]), "r"(af[i][1]), "r"(af[i][2]), "r"(af[i][3]),
                          "r"(bf[j][0]), "r"(bf[j][1]));
        }
        __syncthreads();
    }

    #pragma unroll
    for (int i = 0; i < 2; i++) {
        #pragma unroll
        for (int j = 0; j < 4; j++) {
            const int row = bm + wm + i * 16 + g;
            const int col = bn + wn + j * 8 + t * 2;
            float b0 = 0.f, b1 = 0.f;
            if (d.bias) { b0 = d.bias[col]; b1 = d.bias[col + 1]; }
            float2 v0 = make_float2(acc[i][j][0] + b0, acc[i][j][1] + b1);
            float2 v1 = make_float2(acc[i][j][2] + b0, acc[i][j][3] + b1);
            *(float2*)(d.C + (size_t)row * d.ldc + col) = v0;
            *(float2*)(d.C + (size_t)(row + 8) * d.ldc + col) = v1;
        }
    }
}

// ---------------------------------------------------------------------------
// Batched NN GEMM (prep): C[m,n] = sum_k A[m,k]*B[k,n]  (B row-major [K,N])
// Single-buffered (small workload, 8.3 GF over 496 blocks). grid=(62, 8).
// ---------------------------------------------------------------------------
__global__ void __launch_bounds__(256) gemm_nn_batched(SegParams p, int nseg)
{
    __shared__ float As[128 * 36];
    __shared__ float Bs[64 * 36];

    const int bx = blockIdx.x;
    int si = 0;
    #pragma unroll
    for (int i = 1; i < 12; i++)
        if (i < nseg && bx >= p.seg[i].xStart) si = i;
    const SegDesc d = p.seg[si];

    const int bn = (bx - d.xStart) * 64;
    const int bm = blockIdx.y * 128;
    const int tid  = threadIdx.x;
    const int warp = tid >> 5, lane = tid & 31;
    const int wm = (warp & 3) * 32;
    const int wn = (warp >> 2) * 32;
    const int g = lane >> 2, t = lane & 3;
    const int arow = tid >> 3;
    const int acol = (tid & 7) * 4;

    float acc[2][4][4];
    #pragma unroll
    for (int i = 0; i < 2; i++)
        #pragma unroll
        for (int j = 0; j < 4; j++)
            #pragma unroll
            for (int r = 0; r < 4; r++) acc[i][j][r] = 0.f;

    for (int kt = 0; kt < d.K; kt += 32) {
        #pragma unroll
        for (int r = 0; r < 4; r++) {
            const float4 v = *(const float4*)(d.A + (size_t)(bm + arow + 32 * r) * d.lda + kt + acol);
            float4 w;
            w.x = __uint_as_float(f2tf(v.x));
            w.y = __uint_as_float(f2tf(v.y));
            w.z = __uint_as_float(f2tf(v.z));
            w.w = __uint_as_float(f2tf(v.w));
            *(float4*)(&As[(arow + 32 * r) * 36 + acol]) = w;
        }
        #pragma unroll
        for (int r = 0; r < 2; r++) {
            const int kk = (tid >> 4) + 16 * r;
            const int nn = (tid & 15) * 4;
            const float4 v = *(const float4*)(d.B + (size_t)(kt + kk) * d.ldb + bn + nn);
            Bs[(nn + 0) * 36 + kk] = __uint_as_float(f2tf(v.x));
            Bs[(nn + 1) * 36 + kk] = __uint_as_float(f2tf(v.y));
            Bs[(nn + 2) * 36 + kk] = __uint_as_float(f2tf(v.z));
            Bs[(nn + 3) * 36 + kk] = __uint_as_float(f2tf(v.w));
        }
        __syncthreads();

        #pragma unroll
        for (int ks = 0; ks < 4; ks++) {
            const int k0 = ks * 8;
            unsigned af[2][4], bf[4][2];
            #pragma unroll
            for (int i = 0; i < 2; i++) {
                const int r0 = wm + i * 16;
                af[i][0] = __float_as_uint(As[(r0 + g    ) * 36 + k0 + t]);
                af[i][1] = __float_as_uint(As[(r0 + 8 + g) * 36 + k0 + t]);
                af[i][2] = __float_as_uint(As[(r0 + g    ) * 36 + k0 + t + 4]);
                af[i][3] = __float_as_uint(As[(r0 + 8 + g) * 36 + k0 + t + 4]);
            }
            #pragma unroll
            for (int j = 0; j < 4; j++) {
                const int c0 = wn + j * 8;
                bf[j][0] = __float_as_uint(Bs[(c0 + g) * 36 + k0 + t]);
                bf[j][1] = __float_as_uint(Bs[(c0 + g) * 36 + k0 + t + 4]);
            }
            #pragma unroll
            for (int i = 0; i < 2; i++)
                #pragma unroll
                for (int j = 0; j < 4; j++)
                    asm volatile(
                        "mma.sync.aligned.m16n8k8.row.col.f32.tf32.tf32.f32 "
                        "{%0,%1,%2,%3},{%4,%5,%6,%7},{%8,%9},{%0,%1,%2,%3};\n"
                        : "+f"(acc[i][j][0]), "+f"(acc[i][j][1]),
                          "+f"(acc[i][j][2]), "+f"(acc[i][j][3])
                        : "r"(af[i][0]), "r"(af[i][1]), "r"(af[i][2]), "r"(af[i][3]),
                          "r"(bf[j][0]), "r"(bf[j][1]));
        }
        __syncthreads();
    }

    #pragma unroll
    for (int i = 0; i < 2; i++) {
        #pragma unroll
        for (int j = 0; j < 4; j++) {
            const int row = bm + wm + i * 16 + g;
            const int col = bn + wn + j * 8 + t * 2;
            float2 v0 = make_float2(acc[i][j][0], acc[i][j][1]);
            float2 v1 = make_float2(acc[i][j][2], acc[i][j][3]);
            *(float2*)(d.C + (size_t)row * d.ldc + col) = v0;
            *(float2*)(d.C + (size_t)(row + 8) * d.ldc + col) = v1;
        }
    }
}

// ---------------------------------------------------------------------------
// Fused biases
// ---------------------------------------------------------------------------
__global__ void __launch_bounds__(256) fbias_kernel(
    const float* __restrict__ Wk, const float* __restrict__ bk,
    const float* __restrict__ Wv, const float* __restrict__ bv,
    const float* __restrict__ bs, const float* __restrict__ semb)
{
    const int gw   = blockIdx.x * 8 + (threadIdx.x >> 5);
    const int lane = threadIdx.x & 31;
    const int which = gw / (SS * FD);
    const int rem   = gw - which * (SS * FD);
    const int i = rem >> 10;
    const int f = rem & 1023;
    const float* W = which ? Wv : Wk;
    const float* Wr  = W + (size_t)f * FD;
    const float* bsr = bs + i * FD;
    const float* ser = semb + i * FD;
    float sum = 0.f;
    for (int j = lane; j < FD; j += 32) sum += Wr[j] * (bsr[j] + ser[j]);
    sum = wredsum(sum);
    if (lane == 0) {
        if (which) g_fbv[rem] = sum + bv[f];
        else       g_fbk[rem] = sum + bk[f];
    }
}

// ---------------------------------------------------------------------------
// Attention + scale importance
// ---------------------------------------------------------------------------
__global__ void __launch_bounds__(256) attn_kernel(
    const int* __restrict__ routes, const float* __restrict__ tptr)
{
    const int b = blockIdx.x;
    __shared__ float Qs[FD];
    __shared__ float Ks[SS * FD];
    __shared__ float Vs[SS * FD];
    __shared__ float ssi[SS];
    __shared__ int   rts[SS * LW];
    const int tid = threadIdx.x;

    ((float4*)Qs)[tid] = ((const float4*)(g_Q + (size_t)b * FD))[tid];
    const float4* k4 = (const float4*)(g_K + (size_t)b * SS * FD);
    const float4* v4 = (const float4*)(g_V + (size_t)b * SS * FD);
    #pragma unroll
    for (int i = 0; i < 5; i++) {
        ((float4*)Ks)[tid + 256 * i] = k4[tid + 256 * i];
        ((float4*)Vs)[tid + 256 * i] = v4[tid + 256 * i];
    }
    if (tid < SS * LW) rts[tid] = routes[tid];
    if (tid < SS) ssi[tid] = 0.f;
    __syncthreads();

    const float sc_mul = 1.0f / (8.0f * fabsf(*tptr));
    const int warp = tid >> 5, lane = tid & 31;

    for (int p = warp; p < HH * SS; p += 8) {
        const int h = p / SS, s = p - (p / SS) * SS;
        const float q0 = Qs[h * DD + lane];
        const float q1 = Qs[h * DD + 32 + lane];
        float scw[LW]; int jr[LW];
        #pragma unroll
        for (int w = 0; w < LW; w++) {
            const int j = rts[s * LW + w];
            jr[w] = j;
            const float* kh = Ks + j * FD + h * DD;
            float d = q0 * kh[lane] + q1 * kh[lane + 32];
            d = wredsum(d);
            scw[w] = d * sc_mul;
        }
        const float m = fmaxf(scw[0], fmaxf(scw[1], scw[2]));
        float e0 = expf(scw[0] - m), e1 = expf(scw[1] - m), e2 = expf(scw[2] - m);
        const float inv = 1.0f / (e0 + e1 + e2);
        e0 *= inv; e1 *= inv; e2 *= inv;
        float o0 = 0.f, o1 = 0.f;
        {
            const float* vh = Vs + jr[0] * FD + h * DD;
            o0 += e0 * vh[lane]; o1 += e0 * vh[lane + 32];
        }
        {
            const float* vh = Vs + jr[1] * FD + h * DD;
            o0 += e1 * vh[lane]; o1 += e1 * vh[lane + 32];
        }
        {
            const float* vh = Vs + jr[2] * FD + h * DD;
            o0 += e2 * vh[lane]; o1 += e2 * vh[lane + 32];
        }
        float n2 = o0 * o0 + o1 * o1;
        n2 = wredsum(n2);
        if (lane == 0) atomicAdd(&ssi[s], sqrtf(n2));
    }
    __syncthreads();
    if (tid < SS) g_si[b * SS + tid] = ssi[tid] * (1.0f / (float)HH);
}

// ---------------------------------------------------------------------------
// Gate
// ---------------------------------------------------------------------------
__global__ void __launch_bounds__(128) gate_kernel(
    const float* __restrict__ gamma, const float* __restrict__ beta,
    const float* __restrict__ Wg2, const float* __restrict__ bg2,
    float* __restrict__ outTail)
{
    const int b = blockIdx.x, tid = threadIdx.x;
    const int warp = tid >> 5, lane = tid & 31;
    __shared__ float hs[GD];
    __shared__ float rbuf[32];

    const float4 v  = ((const float4*)(g_H + (size_t)b * GD))[tid];
    float s1 = v.x + v.y + v.z + v.w;
    float s2 = v.x * v.x + v.y * v.y + v.z * v.z + v.w * v.w;
    s1 = wredsum(s1); s2 = wredsum(s2);
    if (lane == 0) { rbuf[warp] = s1; rbuf[4 + warp] = s2; }
    __syncthreads();
    const float mu  = (rbuf[0] + rbuf[1] + rbuf[2] + rbuf[3]) * (1.0f / GD);
    const float ex2 = (rbuf[4] + rbuf[5] + rbuf[6] + rbuf[7]) * (1.0f / GD);
    const float rstd = rsqrtf(ex2 - mu * mu + 1e-5f);

    const float4 ga = ((const float4*)gamma)[tid];
    const float4 be = ((const float4*)beta)[tid];
    float4 o;
    {
        float x;
        x = (v.x - mu) * rstd * ga.x + be.x; o.x = 0.5f * x * (1.f + erff(x * 0.70710678118f));
        x = (v.y - mu) * rstd * ga.y + be.y; o.y = 0.5f * x * (1.f + erff(x * 0.70710678118f));
        x = (v.z - mu) * rstd * ga.z + be.z; o.z = 0.5f * x * (1.f + erff(x * 0.70710678118f));
        x = (v.w - mu) * rstd * ga.w + be.w; o.w = 0.5f * x * (1.f + erff(x * 0.70710678118f));
    }
    ((float4*)hs)[tid] = o;
    __syncthreads();

    float p[SS] = {0.f, 0.f, 0.f, 0.f, 0.f};
    #pragma unroll
    for (int r = 0; r < 4; r++) {
        const float x = hs[tid + 128 * r];
        #pragma unroll
        for (int s = 0; s < SS; s++) p[s] += x * Wg2[s * GD + tid + 128 * r];
    }
    #pragma unroll
    for (int s = 0; s < SS; s++) p[s] = wredsum(p[s]);
    if (lane == 0)
        #pragma unroll
        for (int s = 0; s < SS; s++) rbuf[8 + warp * SS + s] = p[s];
    __syncthreads();

    if (tid == 0) {
        float cs[SS];
        #pragma unroll
        for (int s = 0; s < SS; s++) {
            const float gl = rbuf[8 + s] + rbuf[13 + s] + rbuf[18 + s] + rbuf[23 + s] + bg2[s];
            cs[s] = 0.7f * g_si[b * SS + s] + 0.3f * gl;
        }
        float m = cs[0];
        #pragma unroll
        for (int s = 1; s < SS; s++) m = fmaxf(m, cs[s]);
        float e[SS], tot = 0.f;
        #pragma unroll
        for (int s = 0; s < SS; s++) { e[s] = expf(cs[s] - m); tot += e[s]; }
        const float inv = 1.0f / tot;
        #pragma unroll
        for (int s = 0; s < SS; s++) {
            const float w = e[s] * inv;
            g_aw[b * SS + s] = w;
            outTail[(size_t)b * SS + s] = w;
        }
    }
}

// ---------------------------------------------------------------------------
// combined_logits
// ---------------------------------------------------------------------------
__global__ void __launch_bounds__(256) combine_kernel(
    const float* __restrict__ l0, const float* __restrict__ l1,
    const float* __restrict__ l2, const float* __restrict__ l3,
    const float* __restrict__ l4, float* __restrict__ out)
{
    const int t = blockIdx.x * blockDim.x + threadIdx.x;
    if (t >= BQ * (CC / 4)) return;
    const int b = t / (CC / 4);
    const int c = t - b * (CC / 4);
    const float w0 = g_aw[b * SS + 0], w1 = g_aw[b * SS + 1], w2 = g_aw[b * SS + 2];
    const float w3 = g_aw[b * SS + 3], w4 = g_aw[b * SS + 4];
    const size_t idx = (size_t)b * (CC / 4) + c;
    const float4 a0 = ((const float4*)l0)[idx];
    const float4 a1 = ((const float4*)l1)[idx];
    const float4 a2 = ((const float4*)l2)[idx];
    const float4 a3 = ((const float4*)l3)[idx];
    const float4 a4 = ((const float4*)l4)[idx];
    float4 r;
    r.x = w0 * a0.x + w1 * a1.x + w2 * a2.x + w3 * a3.x + w4 * a4.x;
    r.y = w0 * a0.y + w1 * a1.y + w2 * a2.y + w3 * a3.y + w4 * a4.y;
    r.z = w0 * a0.z + w1 * a1.z + w2 * a2.z + w3 * a3.z + w4 * a4.z;
    r.w = w0 * a0.w + w1 * a1.w + w2 * a2.w + w3 * a3.w + w4 * a4.w;
    ((float4*)out)[idx] = r;
}

// ---------------------------------------------------------------------------
// kernel_launch
// ---------------------------------------------------------------------------
extern "C" void kernel_launch(void* const* d_in, const int* in_sizes, int n_in,
                              void* d_out, int out_size)
{
    (void)in_sizes; (void)n_in; (void)out_size;
    const float* features = (const float*)d_in[0];
    const float* sf[SS]     = {(const float*)d_in[1],  (const float*)d_in[2],
                               (const float*)d_in[3],  (const float*)d_in[4],
                               (const float*)d_in[5]};
    const float* logits[SS] = {(const float*)d_in[6],  (const float*)d_in[7],
                               (const float*)d_in[8],  (const float*)d_in[9],
                               (const float*)d_in[10]};
    const float* Ws[SS]     = {(const float*)d_in[11], (const float*)d_in[12],
                               (const float*)d_in[13], (const float*)d_in[14],
                               (const float*)d_in[15]};
    const float* bs   = (const float*)d_in[16];
    const float* semb = (const float*)d_in[17];
    const float* Wq   = (const float*)d_in[18];
    const float* bq   = (const float*)d_in[19];
    const float* Wk   = (const float*)d_in[20];
    const float* bk   = (const float*)d_in[21];
    const float* Wv   = (const float*)d_in[22];
    const float* bv   = (const float*)d_in[23];
    const float* Wg1  = (const float*)d_in[24];
    const float* bg1  = (const float*)d_in[25];
    const float* gam  = (const float*)d_in[26];
    const float* bet  = (const float*)d_in[27];
    const float* Wg2  = (const float*)d_in[28];
    const float* bg2  = (const float*)d_in[29];
    const float* temp = (const float*)d_in[30];
    const int*   routes = (const int*)d_in[31];

    float *MK, *MV, *fbk, *fbv, *Kb, *Vb, *Qb, *Hb;
    cudaGetSymbolAddress((void**)&MK,  g_MK);
    cudaGetSymbolAddress((void**)&MV,  g_MV);
    cudaGetSymbolAddress((void**)&fbk, g_fbk);
    cudaGetSymbolAddress((void**)&fbv, g_fbv);
    cudaGetSymbolAddress((void**)&Kb,  g_K);
    cudaGetSymbolAddress((void**)&Vb,  g_V);
    cudaGetSymbolAddress((void**)&Qb,  g_Q);
    cudaGetSymbolAddress((void**)&Hb,  g_H);

    static const int SC[SS]  = {64, 128, 256, 512, 1024};
    static const int OFF[SS] = {0, 64, 192, 448, 960};

    // ---- 1) Batched prep: [MK_0..4 | MV_0..4] = [Wk|Wv] @ Ws_i, one launch ----
    {
        SegParams p{};
        int x = 0;
        for (int i = 0; i < SS; i++) {           // MK
            p.seg[i] = {Wk, Ws[i], nullptr, MK + OFF[i], FD, SC[i], CSUM, FD, x};
            x += SC[i] / 64;
        }
        for (int i = 0; i < SS; i++) {           // MV
            p.seg[5 + i] = {Wv, Ws[i], nullptr, MV + OFF[i], FD, SC[i], CSUM, FD, x};
            x += SC[i] / 64;
        }
        gemm_nn_batched<<<dim3(x, FD / 128), 256>>>(p, 10);
    }

    // ---- 2) Fused biases ----
    fbias_kernel<<<(2 * SS * FD) / 8, 256>>>(Wk, bk, Wv, bv, bs, semb);

    // ---- 3) Batched TN: K x5, V x5, Q, H — one launch ----
    {
        SegParams p{};
        int x = 0;
        for (int i = 0; i < SS; i++) {
            p.seg[i] = {sf[i], MK + OFF[i], fbk + i * FD, Kb + i * FD,
                        SC[i], CSUM, SS * FD, SC[i], x};
            x += FD / 64;
        }
        for (int i = 0; i < SS; i++) {
            p.seg[5 + i] = {sf[i], MV + OFF[i], fbv + i * FD, Vb + i * FD,
                            SC[i], CSUM, SS * FD, SC[i], x};
            x += FD / 64;
        }
        p.seg[10] = {features, Wq, bq, Qb, FD, FD, FD, FD, x};
        x += FD / 64;
        p.seg[11] = {features, Wg1, bg1, Hb, FD, FD, GD, FD, x};
        x += GD / 64;

        const int smemBytes = 2 * (128 + 64) * 36 * sizeof(float);  // 55296
        cudaFuncSetAttribute(gemm_tn_batched,
                             cudaFuncAttributeMaxDynamicSharedMemorySize, smemBytes);
        gemm_tn_batched<<<dim3(x, BQ / 128), 256, smemBytes>>>(p, 12);
    }

    // ---- 4) Attention + scale importance ----
    attn_kernel<<<BQ, 256>>>(routes, temp);

    // ---- 5) Gate + softmax -> attention_weights ----
    float* out = (float*)d_out;
    gate_kernel<<<BQ, 128>>>(gam, bet, Wg2, bg2, out + (size_t)BQ * CC);

    // ---- 6) combined_logits ----
    combine_kernel<<<(BQ * (CC / 4) + 255) / 256, 256>>>(logits[0], logits[1], logits[2],
                                                         logits[3], logits[4], out);
}